// round 4
// baseline (speedup 1.0000x reference)
#include <cuda_runtime.h>
#include <cuda_bf16.h>

#define N_NODES 100000
#define N_EDGES 1000000
#define DIM 64
#define EDIM 16
#define SCAN_BS 512
#define SCAN_NBLK ((N_NODES + SCAN_BS - 1) / SCAN_BS)   // 196

// Flag: 1 if edge_index is int64, 0 if int32.
__device__ int g_idx_is64;

// CSR scratch (static device globals -- no allocation)
__device__ int  g_cnt[N_NODES];
__device__ int  g_off[N_NODES];
__device__ int  g_cur[N_NODES];
__device__ int  g_bsum[SCAN_NBLK];
__device__ int  g_bbase[SCAN_NBLK];
__device__ int2 g_epack[N_EDGES];      // (edge id, src)

// ---------------------------------------------------------------------------
// packed fp32x2 helpers (Blackwell FFMA2)
// ---------------------------------------------------------------------------
__device__ __forceinline__ unsigned long long f2_as_u64(float a, float b) {
    unsigned long long r;
    asm("mov.b64 %0, {%1, %2};" : "=l"(r) : "f"(a), "f"(b));
    return r;
}
__device__ __forceinline__ void u64_as_f2(unsigned long long v, float& a, float& b) {
    asm("mov.b64 {%0, %1}, %2;" : "=f"(a), "=f"(b) : "l"(v));
}
__device__ __forceinline__ void ffma2(unsigned long long& d,
                                      unsigned long long a, unsigned long long b) {
    asm("fma.rn.f32x2 %0, %1, %2, %0;" : "+l"(d) : "l"(a), "l"(b));
}

// ---------------------------------------------------------------------------
// Kernel 0: detect index dtype (int64 node ids < 1e5 -> high words all zero)
// ---------------------------------------------------------------------------
__global__ void detect_kernel(const unsigned int* __restrict__ w) {
    __shared__ unsigned int nz[8];
    unsigned int v = w[2 * threadIdx.x + 1];
    unsigned int any = __ballot_sync(0xffffffffu, v != 0u);
    if ((threadIdx.x & 31) == 0) nz[threadIdx.x >> 5] = any;
    __syncthreads();
    if (threadIdx.x == 0) {
        unsigned int a = 0;
#pragma unroll
        for (int i = 0; i < 8; i++) a |= nz[i];
        g_idx_is64 = (a == 0u) ? 1 : 0;
    }
}

// ---------------------------------------------------------------------------
// CSR pass A: zero histogram
// ---------------------------------------------------------------------------
__global__ void zero_cnt_kernel() {
    int i = blockIdx.x * 256 + threadIdx.x;
    if (i < N_NODES) g_cnt[i] = 0;
}

// ---------------------------------------------------------------------------
// CSR pass B: histogram of dst
// ---------------------------------------------------------------------------
__global__ void hist_kernel(const void* __restrict__ ei_raw) {
    int e = blockIdx.x * 256 + threadIdx.x;
    if (e >= N_EDGES) return;
    int dst = g_idx_is64 ? (int)((const long long*)ei_raw)[N_EDGES + e]
                         : ((const int*)ei_raw)[N_EDGES + e];
    atomicAdd(&g_cnt[dst], 1);
}

// ---------------------------------------------------------------------------
// CSR pass C: 3-step exclusive scan of g_cnt -> g_off (and g_cur copy)
// ---------------------------------------------------------------------------
__global__ void scan1_kernel() {                 // block sums
    __shared__ int sh[SCAN_BS];
    int idx = blockIdx.x * SCAN_BS + threadIdx.x;
    sh[threadIdx.x] = (idx < N_NODES) ? g_cnt[idx] : 0;
    __syncthreads();
    for (int o = SCAN_BS / 2; o > 0; o >>= 1) {
        if (threadIdx.x < o) sh[threadIdx.x] += sh[threadIdx.x + o];
        __syncthreads();
    }
    if (threadIdx.x == 0) g_bsum[blockIdx.x] = sh[0];
}

__global__ void scan2_kernel() {                 // serial scan of 196 partials
    if (threadIdx.x == 0) {
        int s = 0;
        for (int i = 0; i < SCAN_NBLK; i++) { g_bbase[i] = s; s += g_bsum[i]; }
    }
}

__global__ void scan3_kernel() {                 // per-block exclusive scan
    __shared__ int sh[SCAN_BS];
    int idx = blockIdx.x * SCAN_BS + threadIdx.x;
    int v = (idx < N_NODES) ? g_cnt[idx] : 0;
    sh[threadIdx.x] = v;
    __syncthreads();
    for (int o = 1; o < SCAN_BS; o <<= 1) {      // Hillis-Steele inclusive
        int t = (threadIdx.x >= o) ? sh[threadIdx.x - o] : 0;
        __syncthreads();
        sh[threadIdx.x] += t;
        __syncthreads();
    }
    if (idx < N_NODES) {
        int ex = g_bbase[blockIdx.x] + sh[threadIdx.x] - v;
        g_off[idx] = ex;
        g_cur[idx] = ex;
    }
}

// ---------------------------------------------------------------------------
// CSR pass D: scatter edges into dst-sorted order
// ---------------------------------------------------------------------------
__global__ void build_kernel(const void* __restrict__ ei_raw) {
    int e = blockIdx.x * 256 + threadIdx.x;
    if (e >= N_EDGES) return;
    int src, dst;
    if (g_idx_is64) {
        const long long* ei = (const long long*)ei_raw;
        src = (int)ei[e];
        dst = (int)ei[N_EDGES + e];
    } else {
        const int* ei = (const int*)ei_raw;
        src = ei[e];
        dst = ei[N_EDGES + e];
    }
    int pos = atomicAdd(&g_cur[dst], 1);
    g_epack[pos] = make_int2(e, src);
}

// ---------------------------------------------------------------------------
// Aggregate: per-node gather + message compute, NO float atomics.
// 2 nodes per warp: group = lane>>4 owns node 2w+group; lane l=lane&15 owns
// cols [4l..4l+4) as two packed f32x2 accumulators.
//   msg = relu(x[src] + ea @ We + be);  out[n] = sum msg
// ---------------------------------------------------------------------------
__global__ __launch_bounds__(256) void aggregate_kernel(
    const float4* __restrict__ x4,
    const float*  __restrict__ ea,
    const float4* __restrict__ We4,
    const float4* __restrict__ be4,
    float4* __restrict__ out4)
{
    __shared__ float4 Wes[EDIM * 16];   // We row-major verbatim, 4 KB

    int tid = threadIdx.x;
    for (int i = tid; i < EDIM * 16; i += 256) Wes[i] = We4[i];
    __syncthreads();

    int w    = blockIdx.x * 8 + (tid >> 5);
    int lane = tid & 31;
    int grp  = lane >> 4, l = lane & 15;
    int n    = w * 2 + grp;                        // exact grid: n < N_NODES

    int off = g_off[n], deg = g_cnt[n];
    int degmax = max(deg, __shfl_xor_sync(0xffffffffu, deg, 16));

    ulonglong2 be2 = ((const ulonglong2*)be4)[l];
    float4 acc = make_float4(0.f, 0.f, 0.f, 0.f);

    for (int j = 0; j < degmax; j++) {
        if (j < deg) {
            int2 es = __ldcs(&g_epack[off + j]);   // (eid, src), uniform/group
            const float4* ear = (const float4*)ea + es.x * 4;
            float4 A0 = __ldcs(ear + 0);
            float4 A1 = __ldcs(ear + 1);
            float4 A2 = __ldcs(ear + 2);
            float4 A3 = __ldcs(ear + 3);

            unsigned long long p0 = be2.x, p1 = be2.y;
#define STEP(k, a) { unsigned long long av = f2_as_u64((a), (a));              \
                     ulonglong2 wv = *(const ulonglong2*)&Wes[(k) * 16 + l];   \
                     ffma2(p0, av, wv.x); ffma2(p1, av, wv.y); }
            STEP(0,  A0.x) STEP(1,  A0.y) STEP(2,  A0.z) STEP(3,  A0.w)
            STEP(4,  A1.x) STEP(5,  A1.y) STEP(6,  A1.z) STEP(7,  A1.w)
            STEP(8,  A2.x) STEP(9,  A2.y) STEP(10, A2.z) STEP(11, A2.w)
            STEP(12, A3.x) STEP(13, A3.y) STEP(14, A3.z) STEP(15, A3.w)
#undef STEP
            float4 xv = x4[es.y * 16 + l];
            float m0, m1, m2, m3;
            u64_as_f2(p0, m0, m1);
            u64_as_f2(p1, m2, m3);
            acc.x += fmaxf(m0 + xv.x, 0.f);
            acc.y += fmaxf(m1 + xv.y, 0.f);
            acc.z += fmaxf(m2 + xv.z, 0.f);
            acc.w += fmaxf(m3 + xv.w, 0.f);
        }
    }
    out4[(size_t)n * 16 + l] = acc;
}

// ---------------------------------------------------------------------------
// Node epilogue: 8 nodes/warp, packed f32x2 MLP + LayerNorm + ReLU (as R3)
// ---------------------------------------------------------------------------
#define NPW 8
__global__ __launch_bounds__(256, 4) void node_kernel(
    const float2* __restrict__ x,
    const float* __restrict__ W1,
    const float* __restrict__ b1,
    const float* __restrict__ W2,
    const float* __restrict__ b2,
    const float* __restrict__ gamma,
    const float* __restrict__ beta,
    float2* __restrict__ out)     // holds aggr on entry; overwritten in place
{
    __shared__ unsigned long long W1p[32 * 64];   // 16 KB
    __shared__ unsigned long long W2p[32 * 64];   // 16 KB
    __shared__ float hs[8][NPW * DIM];            // 16 KB

    int tid = threadIdx.x;
    for (int i = tid; i < 32 * 64; i += 256) {
        int k2 = i >> 6, c = i & 63;
        W1p[i] = f2_as_u64(W1[(2 * k2) * 64 + c], W1[(2 * k2 + 1) * 64 + c]);
        W2p[i] = f2_as_u64(W2[(2 * k2) * 64 + c], W2[(2 * k2 + 1) * 64 + c]);
    }
    __syncthreads();

    int w = tid >> 5, lane = tid & 31;
    int base = (blockIdx.x * 8 + w) * NPW;
    if (base >= N_NODES) return;
    float* h = hs[w];

#pragma unroll
    for (int n = 0; n < NPW; n++) {
        int node = base + n;
        if (node < N_NODES) {
            float2 xv = x[(size_t)node * 32 + lane];
            float2 av = out[(size_t)node * 32 + lane];
            *(float2*)&h[n * DIM + 2 * lane] = make_float2(xv.x + av.x, xv.y + av.y);
        }
    }
    __syncwarp();

    unsigned long long accA[NPW], accB[NPW];

    // ---- layer 1 ----
    {
        float bA = b1[2 * lane], bB = b1[2 * lane + 1];
#pragma unroll
        for (int n = 0; n < NPW; n++) {
            accA[n] = f2_as_u64(bA, 0.f);
            accB[n] = f2_as_u64(bB, 0.f);
        }
    }
#pragma unroll
    for (int k2 = 0; k2 < 32; k2++) {
        ulonglong2 wp = *(const ulonglong2*)&W1p[k2 * 64 + 2 * lane];
#pragma unroll
        for (int n = 0; n < NPW; n++) {
            unsigned long long h2 = *(const unsigned long long*)&h[n * DIM + 2 * k2];
            ffma2(accA[n], h2, wp.x);
            ffma2(accB[n], h2, wp.y);
        }
    }
    __syncwarp();
#pragma unroll
    for (int n = 0; n < NPW; n++) {
        float ax, ay, bx, by;
        u64_as_f2(accA[n], ax, ay);
        u64_as_f2(accB[n], bx, by);
        *(float2*)&h[n * DIM + 2 * lane] =
            make_float2(fmaxf(ax + ay, 0.f), fmaxf(bx + by, 0.f));
    }
    __syncwarp();

    // ---- layer 2 ----
    {
        float bA = b2[2 * lane], bB = b2[2 * lane + 1];
#pragma unroll
        for (int n = 0; n < NPW; n++) {
            accA[n] = f2_as_u64(bA, 0.f);
            accB[n] = f2_as_u64(bB, 0.f);
        }
    }
#pragma unroll
    for (int k2 = 0; k2 < 32; k2++) {
        ulonglong2 wp = *(const ulonglong2*)&W2p[k2 * 64 + 2 * lane];
#pragma unroll
        for (int n = 0; n < NPW; n++) {
            unsigned long long h2 = *(const unsigned long long*)&h[n * DIM + 2 * k2];
            ffma2(accA[n], h2, wp.x);
            ffma2(accB[n], h2, wp.y);
        }
    }

    // ---- LayerNorm + ReLU ----
    float2 g  = make_float2(gamma[2 * lane], gamma[2 * lane + 1]);
    float2 bt = make_float2(beta[2 * lane],  beta[2 * lane + 1]);
    const float inv = 1.0f / DIM;

#pragma unroll
    for (int n = 0; n < NPW; n++) {
        float ax, ay, bx, by;
        u64_as_f2(accA[n], ax, ay);
        u64_as_f2(accB[n], bx, by);
        float v0 = ax + ay, v1 = bx + by;
        float s = v0 + v1, q = v0 * v0 + v1 * v1;
#pragma unroll
        for (int o = 16; o > 0; o >>= 1) {
            s += __shfl_xor_sync(0xffffffffu, s, o);
            q += __shfl_xor_sync(0xffffffffu, q, o);
        }
        float mu  = s * inv;
        float var = fmaxf(q * inv - mu * mu, 0.f);
        float r   = rsqrtf(var + 1e-5f);
        int node = base + n;
        if (node < N_NODES) {
            float2 o2;
            o2.x = fmaxf((v0 - mu) * r * g.x + bt.x, 0.f);
            o2.y = fmaxf((v1 - mu) * r * g.y + bt.y, 0.f);
            out[(size_t)node * 32 + lane] = o2;
        }
    }
}

// ---------------------------------------------------------------------------
// Launch
// ---------------------------------------------------------------------------
extern "C" void kernel_launch(void* const* d_in, const int* in_sizes, int n_in,
                              void* d_out, int out_size) {
    const float* x     = (const float*)d_in[0];
    const void*  ei    = d_in[1];
    const float* ea    = (const float*)d_in[2];
    const float* We    = (const float*)d_in[3];
    const float* be    = (const float*)d_in[4];
    const float* W1    = (const float*)d_in[5];
    const float* b1    = (const float*)d_in[6];
    const float* W2    = (const float*)d_in[7];
    const float* b2    = (const float*)d_in[8];
    const float* gamma = (const float*)d_in[9];
    const float* beta  = (const float*)d_in[10];
    float* out = (float*)d_out;

    detect_kernel<<<1, 256>>>((const unsigned int*)ei);

    // CSR build: histogram -> scan -> scatter
    zero_cnt_kernel<<<(N_NODES + 255) / 256, 256>>>();
    hist_kernel<<<(N_EDGES + 255) / 256, 256>>>(ei);
    scan1_kernel<<<SCAN_NBLK, SCAN_BS>>>();
    scan2_kernel<<<1, 32>>>();
    scan3_kernel<<<SCAN_NBLK, SCAN_BS>>>();
    build_kernel<<<(N_EDGES + 255) / 256, 256>>>(ei);

    // Gather-aggregate (no float atomics): 2 nodes/warp, 16 nodes/block
    aggregate_kernel<<<N_NODES / 16, 256>>>((const float4*)x, ea,
                                            (const float4*)We, (const float4*)be,
                                            (float4*)out);

    // Node MLP + LayerNorm: 64 nodes/block
    node_kernel<<<(N_NODES + 63) / 64, 256>>>((const float2*)x, W1, b1, W2, b2,
                                              gamma, beta, (float2*)out);
}